// round 3
// baseline (speedup 1.0000x reference)
#include <cuda_runtime.h>
#include <float.h>

// _VQ_29609504538631 : fused VQ-VAE bottleneck (precision-hardened argmax)
//   e  = in_w @ z[b,:,t] + in_b            (D=8 x C=1024)
//   id = argmin_k ||e - cb[k]||^2          (K=1024, D=8)
//   out[b,:,t] = out_w @ cb[id] + out_b    (C=1024 x D=8)
//
// Argmax hardening: chunked fp32 + double-merge for e, double half-norms,
// and an exact fp64 rescore of the fp32 top-2 candidates.

namespace {
constexpr int Bb = 8;
constexpr int Cc = 1024;
constexpr int Tt = 8192;
constexpr int Kk = 1024;
constexpr int Dd = 8;
constexpr int TT = 256;   // time positions per block
constexpr int NT = 256;   // threads per block
constexpr int CHUNK = 64; // fp32 accumulation chunk for e
}

__global__ __launch_bounds__(NT) void vq_fused(
    const float* __restrict__ z,
    const float* __restrict__ in_w,    // [D, C]
    const float* __restrict__ in_b,    // [D]
    const float* __restrict__ cb,      // [K, D]
    const float* __restrict__ out_w,   // [C, D]
    const float* __restrict__ out_b,   // [C]
    float* __restrict__ out,           // [B, C, T]
    float* __restrict__ ids_out)       // [B, T] (as float), may be null
{
    __shared__ float buf[Dd * Cc];   // 32 KB, reused: in_w -> codebook -> out_w
    __shared__ float aux[Kk];        // half-norms (phase 2) / out_b (phase 3)
    __shared__ float bias_in[Dd];

    const int tid = threadIdx.x;
    const int b   = blockIdx.x / (Tt / TT);
    const int t   = (blockIdx.x % (Tt / TT)) * TT + tid;

    // ---- Phase 0: stage in_w transposed -> buf[c*8+d]
    for (int i = tid; i < Dd * Cc; i += NT) {
        int d = i & 7, c = i >> 3;
        buf[i] = in_w[d * Cc + c];
    }
    if (tid < Dd) bias_in[tid] = in_b[tid];
    __syncthreads();

    // ---- Phase 1: e[d] = sum_c in_w[d][c] * z[b][c][t]
    // fp32 within 64-chunks, chunk sums merged in fp64 (near-exact reduction).
    double e_d[Dd];
    #pragma unroll
    for (int d = 0; d < Dd; d++) e_d[d] = 0.0;

    const float* zp = z + (size_t)b * Cc * Tt + t;
    for (int c0 = 0; c0 < Cc; c0 += CHUNK) {
        float acc[Dd];
        #pragma unroll
        for (int d = 0; d < Dd; d++) acc[d] = 0.0f;
        #pragma unroll 8
        for (int cc = 0; cc < CHUNK; cc++) {
            int c = c0 + cc;
            float v = __ldg(zp + (size_t)c * Tt);
            const float4* w4 = reinterpret_cast<const float4*>(buf + c * 8);
            float4 w0 = w4[0];
            float4 w1 = w4[1];
            acc[0] = fmaf(v, w0.x, acc[0]);
            acc[1] = fmaf(v, w0.y, acc[1]);
            acc[2] = fmaf(v, w0.z, acc[2]);
            acc[3] = fmaf(v, w0.w, acc[3]);
            acc[4] = fmaf(v, w1.x, acc[4]);
            acc[5] = fmaf(v, w1.y, acc[5]);
            acc[6] = fmaf(v, w1.z, acc[6]);
            acc[7] = fmaf(v, w1.w, acc[7]);
        }
        #pragma unroll
        for (int d = 0; d < Dd; d++) e_d[d] += (double)acc[d];
    }
    // round to fp32 (reference's enc is fp32); bias added in fp64 first
    float e32[Dd];
    #pragma unroll
    for (int d = 0; d < Dd; d++) e32[d] = (float)(e_d[d] + (double)bias_in[d]);
    __syncthreads();  // done reading buf (in_w)

    // ---- Phase 2a: stage codebook + half-norms (norms in fp64, rounded once)
    for (int k = tid; k < Kk; k += NT) {
        float4 c0 = __ldg(reinterpret_cast<const float4*>(cb + k * 8));
        float4 c1 = __ldg(reinterpret_cast<const float4*>(cb + k * 8) + 1);
        reinterpret_cast<float4*>(buf)[k * 2]     = c0;
        reinterpret_cast<float4*>(buf)[k * 2 + 1] = c1;
        double n = (double)c0.x*c0.x + (double)c0.y*c0.y
                 + (double)c0.z*c0.z + (double)c0.w*c0.w
                 + (double)c1.x*c1.x + (double)c1.y*c1.y
                 + (double)c1.z*c1.z + (double)c1.w*c1.w;
        aux[k] = (float)(0.5 * n);
    }
    __syncthreads();

    // ---- Phase 2b: argmin_k dist == argmax_k (e.cb[k] - 0.5||cb[k]||^2)
    // fp32 scan keeps top-2; fp64 rescore resolves near-ties exactly.
    float best1 = -FLT_MAX, best2 = -FLT_MAX;
    int   bi1 = 0, bi2 = 0;
    #pragma unroll 4
    for (int k = 0; k < Kk; k++) {
        const float4* c4 = reinterpret_cast<const float4*>(buf + k * 8);
        float4 c0 = c4[0];
        float4 c1 = c4[1];
        float dot;
        dot = fmaf(e32[0], c0.x, 0.0f);
        dot = fmaf(e32[1], c0.y, dot);
        dot = fmaf(e32[2], c0.z, dot);
        dot = fmaf(e32[3], c0.w, dot);
        dot = fmaf(e32[4], c1.x, dot);
        dot = fmaf(e32[5], c1.y, dot);
        dot = fmaf(e32[6], c1.z, dot);
        dot = fmaf(e32[7], c1.w, dot);
        float s = dot - aux[k];
        if (s > best1) {
            best2 = best1; bi2 = bi1;
            best1 = s;     bi1 = k;
        } else if (s > best2) {
            best2 = s;     bi2 = k;
        }
    }

    // fp64 refine of the two candidates (exact ordering on fp32 e)
    {
        double s_c[2];
        int    k_c[2] = {bi1, bi2};
        #pragma unroll
        for (int j = 0; j < 2; j++) {
            const float* w = buf + k_c[j] * 8;
            double dot = 0.0, nrm = 0.0;
            #pragma unroll
            for (int i = 0; i < Dd; i++) {
                double wi = (double)w[i];
                dot += (double)e32[i] * wi;
                nrm += wi * wi;
            }
            s_c[j] = dot - 0.5 * nrm;
        }
        if (s_c[1] > s_c[0] || (s_c[1] == s_c[0] && bi2 < bi1)) bi1 = bi2;
    }
    const int bi = bi1;

    // grab winning code before buf is overwritten
    float q[Dd];
    {
        const float4* c4 = reinterpret_cast<const float4*>(buf + bi * 8);
        float4 c0 = c4[0];
        float4 c1 = c4[1];
        q[0]=c0.x; q[1]=c0.y; q[2]=c0.z; q[3]=c0.w;
        q[4]=c1.x; q[5]=c1.y; q[6]=c1.z; q[7]=c1.w;
    }
    __syncthreads();  // done reading buf (codebook)

    // ---- Phase 3a: stage out_w ([C,D] layout already c*8+d) and out_b
    for (int i = tid; i < Cc * Dd; i += NT) buf[i] = out_w[i];
    for (int i = tid; i < Cc; i += NT)      aux[i] = out_b[i];
    __syncthreads();

    // ---- Phase 3b: out[b][c][t] = q . out_w[c,:] + out_b[c]
    float* op = out + (size_t)b * Cc * Tt + t;
    #pragma unroll 8
    for (int c = 0; c < Cc; c++) {
        const float4* w4 = reinterpret_cast<const float4*>(buf + c * 8);
        float4 w0 = w4[0];
        float4 w1 = w4[1];
        float s;
        s = fmaf(q[0], w0.x, 0.0f);
        s = fmaf(q[1], w0.y, s);
        s = fmaf(q[2], w0.z, s);
        s = fmaf(q[3], w0.w, s);
        s = fmaf(q[4], w1.x, s);
        s = fmaf(q[5], w1.y, s);
        s = fmaf(q[6], w1.z, s);
        s = fmaf(q[7], w1.w, s);
        op[(size_t)c * Tt] = s + aux[c];
    }

    if (ids_out) ids_out[(size_t)b * Tt + t] = (float)bi;
}

extern "C" void kernel_launch(void* const* d_in, const int* in_sizes, int n_in,
                              void* d_out, int out_size) {
    const float* z     = (const float*)d_in[0];
    const float* in_w  = (const float*)d_in[1];
    const float* in_b  = (const float*)d_in[2];
    const float* cb    = (const float*)d_in[3];
    const float* out_w = (const float*)d_in[4];
    const float* out_b = (const float*)d_in[5];

    float* out = (float*)d_out;
    const long long out_elems = (long long)Bb * Cc * Tt;
    float* ids = (out_size > out_elems) ? out + out_elems : nullptr;

    dim3 grid(Bb * (Tt / TT));
    vq_fused<<<grid, NT>>>(z, in_w, in_b, cb, out_w, out_b, out, ids);
}